// round 16
// baseline (speedup 1.0000x reference)
#include <cuda_runtime.h>
#include <cuda_bf16.h>
#include <math.h>
#include <cstdint>

// ---------------------------------------------------------------------------
// Problem constants
// ---------------------------------------------------------------------------
#define S_IMG 2048
#define S_TXT 256
#define S_ALL 2304
#define HID   3072
#define NH    24
#define HD    128
#define MLPD  12288
#define QKV3  9216
#define MOD6  18432
#define EPS   1e-6f
#define IMGOFF ((size_t)S_IMG * HID)
#define MBI   (S_IMG / 128)
#define MBALL (S_ALL / 128)

// ---------------------------------------------------------------------------
// Static scratch
// ---------------------------------------------------------------------------
__device__ float g_mod_i[MOD6];
__device__ float g_mod_t[MOD6];
__device__ float g_qkv [(size_t)S_ALL * QKV3];
__device__ float g_res [(size_t)S_ALL * HID];

__device__ __align__(16) __nv_bfloat16 g_qh[(size_t)NH * S_ALL * HD];
__device__ __align__(16) __nv_bfloat16 g_ql[(size_t)NH * S_ALL * HD];
__device__ __align__(16) __nv_bfloat16 g_kh[(size_t)NH * S_ALL * HD];
__device__ __align__(16) __nv_bfloat16 g_kl[(size_t)NH * S_ALL * HD];
__device__ __align__(16) __nv_bfloat16 g_vh[(size_t)NH * S_ALL * HD];
__device__ __align__(16) __nv_bfloat16 g_vl[(size_t)NH * S_ALL * HD];

__device__ __align__(16) __nv_bfloat16 g_xln_h[(size_t)S_ALL * HID];
__device__ __align__(16) __nv_bfloat16 g_xln_l[(size_t)S_ALL * HID];
__device__ __align__(16) __nv_bfloat16 g_x2_h [(size_t)S_ALL * HID];
__device__ __align__(16) __nv_bfloat16 g_x2_l [(size_t)S_ALL * HID];
__device__ __align__(16) __nv_bfloat16 g_at_h [(size_t)S_ALL * HID];
__device__ __align__(16) __nv_bfloat16 g_at_l [(size_t)S_ALL * HID];
__device__ __align__(16) __nv_bfloat16 g_hh   [(size_t)S_ALL * MLPD];
__device__ __align__(16) __nv_bfloat16 g_hl   [(size_t)S_ALL * MLPD];

__device__ __align__(16) __nv_bfloat16 g_wiqkv_h[(size_t)HID * QKV3];
__device__ __align__(16) __nv_bfloat16 g_wiqkv_l[(size_t)HID * QKV3];
__device__ __align__(16) __nv_bfloat16 g_wipro_h[(size_t)HID * HID];
__device__ __align__(16) __nv_bfloat16 g_wipro_l[(size_t)HID * HID];
__device__ __align__(16) __nv_bfloat16 g_wiw1_h [(size_t)HID * MLPD];
__device__ __align__(16) __nv_bfloat16 g_wiw1_l [(size_t)HID * MLPD];
__device__ __align__(16) __nv_bfloat16 g_wiw2_h [(size_t)MLPD * HID];
__device__ __align__(16) __nv_bfloat16 g_wiw2_l [(size_t)MLPD * HID];
__device__ __align__(16) __nv_bfloat16 g_wtqkv_h[(size_t)HID * QKV3];
__device__ __align__(16) __nv_bfloat16 g_wtqkv_l[(size_t)HID * QKV3];
__device__ __align__(16) __nv_bfloat16 g_wtpro_h[(size_t)HID * HID];
__device__ __align__(16) __nv_bfloat16 g_wtpro_l[(size_t)HID * HID];
__device__ __align__(16) __nv_bfloat16 g_wtw1_h [(size_t)HID * MLPD];
__device__ __align__(16) __nv_bfloat16 g_wtw1_l [(size_t)HID * MLPD];
__device__ __align__(16) __nv_bfloat16 g_wtw2_h [(size_t)MLPD * HID];
__device__ __align__(16) __nv_bfloat16 g_wtw2_l [(size_t)MLPD * HID];

// ---------------------------------------------------------------------------
// PTX helpers
// ---------------------------------------------------------------------------
__device__ __forceinline__ uint32_t smem_u32(const void* p) {
    uint32_t a;
    asm("{ .reg .u64 t; cvta.to.shared.u64 t, %1; cvt.u32.u64 %0, t; }"
        : "=r"(a) : "l"(p));
    return a;
}
__device__ __forceinline__ void ldsm_x4(uint32_t* r, uint32_t addr) {
    asm volatile("ldmatrix.sync.aligned.m8n8.x4.shared.b16 {%0,%1,%2,%3}, [%4];"
        : "=r"(r[0]), "=r"(r[1]), "=r"(r[2]), "=r"(r[3]) : "r"(addr));
}
__device__ __forceinline__ void ldsm_x2(uint32_t* r, uint32_t addr) {
    asm volatile("ldmatrix.sync.aligned.m8n8.x2.shared.b16 {%0,%1}, [%2];"
        : "=r"(r[0]), "=r"(r[1]) : "r"(addr));
}
__device__ __forceinline__ void ldsm_x2_t(uint32_t* r, uint32_t addr) {
    asm volatile("ldmatrix.sync.aligned.m8n8.x2.trans.shared.b16 {%0,%1}, [%2];"
        : "=r"(r[0]), "=r"(r[1]) : "r"(addr));
}
__device__ __forceinline__ void mma_bf16(float* d, const uint32_t* a,
                                         const uint32_t* b) {
    asm volatile("mma.sync.aligned.m16n8k16.row.col.f32.bf16.bf16.f32 "
        "{%0,%1,%2,%3}, {%4,%5,%6,%7}, {%8,%9}, {%0,%1,%2,%3};"
        : "+f"(d[0]), "+f"(d[1]), "+f"(d[2]), "+f"(d[3])
        : "r"(a[0]), "r"(a[1]), "r"(a[2]), "r"(a[3]), "r"(b[0]), "r"(b[1]));
}
#define CP16(dst, src) \
    asm volatile("cp.async.cg.shared.global [%0], [%1], 16;" \
                 :: "r"(dst), "l"(src))
#define CP_COMMIT() asm volatile("cp.async.commit_group;" ::: "memory")
#define CP_WAIT1()  asm volatile("cp.async.wait_group 1;" ::: "memory")
#define CP_WAIT0()  asm volatile("cp.async.wait_group 0;" ::: "memory")

__device__ __forceinline__ __nv_bfloat162 bf2hi(float a, float b,
                                                __nv_bfloat162& lo) {
    __nv_bfloat16 ha = __float2bfloat16_rn(a);
    __nv_bfloat16 hb = __float2bfloat16_rn(b);
    lo.x = __float2bfloat16_rn(a - __bfloat162float(ha));
    lo.y = __float2bfloat16_rn(b - __bfloat162float(hb));
    __nv_bfloat162 h; h.x = ha; h.y = hb;
    return h;
}

// ---------------------------------------------------------------------------
// weight split (paired img/txt via grid.y)
// ---------------------------------------------------------------------------
__global__ void k_split4b(const float4* __restrict__ wi,
                          __nv_bfloat162* __restrict__ hi_i,
                          __nv_bfloat162* __restrict__ lo_i,
                          const float4* __restrict__ wt,
                          __nv_bfloat162* __restrict__ hi_t,
                          __nv_bfloat162* __restrict__ lo_t)
{
    const float4* w = blockIdx.y ? wt : wi;
    __nv_bfloat162* hi = blockIdx.y ? hi_t : hi_i;
    __nv_bfloat162* lo = blockIdx.y ? lo_t : lo_i;
    int i = blockIdx.x * 256 + threadIdx.x;
    float4 v = w[i];
    __nv_bfloat162 l0, l1;
    __nv_bfloat162 h0 = bf2hi(v.x, v.y, l0);
    __nv_bfloat162 h1 = bf2hi(v.z, v.w, l1);
    hi[2 * i] = h0; hi[2 * i + 1] = h1;
    lo[2 * i] = l0; lo[2 * i + 1] = l1;
}

// ---------------------------------------------------------------------------
// merged split-bf16 HMMA GEMM.
// GRID: x = M-blocks (18), y = N-strips  -> consecutive CTAs share B strip.
// EPI: 0 bias->fp32; 1 bias+gelu->bf16 hi/lo; 2 res+gate*(acc+bias)->fp32
// ---------------------------------------------------------------------------
#define LDA_T 40
#define LDB_T 136
#define A_BYTES (128 * LDA_T * 2)
#define B_BYTES (32 * LDB_T * 2)
#define BUF_BYTES (2 * A_BYTES + 2 * B_BYTES)   // 37888
#define GEMM_SMEM (3 * BUF_BYTES)               // 113664

template<int EPI>
__global__ void __launch_bounds__(256, 2)
k_gemm2(const __nv_bfloat16* __restrict__ Ahi,
        const __nv_bfloat16* __restrict__ Alo,
        const __nv_bfloat16* __restrict__ Bhi_i,
        const __nv_bfloat16* __restrict__ Bli_i,
        const __nv_bfloat16* __restrict__ Bhi_t,
        const __nv_bfloat16* __restrict__ Bli_t,
        const float* __restrict__ bias_i, const float* __restrict__ bias_t,
        const float* __restrict__ res_i,  const float* __restrict__ res_t,
        const float* __restrict__ gate_i, const float* __restrict__ gate_t,
        float* __restrict__ C,
        __nv_bfloat16* __restrict__ Chi, __nv_bfloat16* __restrict__ Clo,
        int N, int K)
{
    extern __shared__ char smc[];
    const uint32_t sb = smem_u32(smc);
    const int tid = threadIdx.x, warp = tid >> 5, lane = tid & 31;
    const int wm = warp & 1, wn = warp >> 1;
    const int bx = blockIdx.y, by = blockIdx.x;   // SWAPPED: x=M, y=N
    const int nch = K >> 5;

    const bool isimg = (by < MBI);
    const __nv_bfloat16* Bh = isimg ? Bhi_i : Bhi_t;
    const __nv_bfloat16* Bl = isimg ? Bli_i : Bli_t;
    const float* bias = isimg ? bias_i : bias_t;
    const float* resb = isimg ? res_i  : res_t;
    const float* gate = isimg ? gate_i : gate_t;
    const size_t aRow0 = (size_t)by * 128;
    const size_t rRow0 = isimg ? aRow0 : (size_t)(by - MBI) * 128;

    const __nv_bfloat16* gAh = Ahi + aRow0 * K;
    const __nv_bfloat16* gAl = Alo + aRow0 * K;
    const __nv_bfloat16* gBh = Bh + bx * 128;
    const __nv_bfloat16* gBl = Bl + bx * 128;

    const int ar = tid >> 1;
    const int ac = (tid & 1) * 16;
    const int bk = tid >> 3;
    const int bn = (tid & 7) * 16;

    float acc[4][4][4];
    #pragma unroll
    for (int i = 0; i < 4; i++)
        #pragma unroll
        for (int j = 0; j < 4; j++)
            #pragma unroll
            for (int r = 0; r < 4; r++) acc[i][j][r] = 0.f;

    auto issue = [&](int c) {
        const int k0 = c << 5;
        const uint32_t base = sb + (c % 3) * BUF_BYTES;
        {
            const __nv_bfloat16* ga = gAh + (size_t)ar * K + k0 + ac;
            uint32_t da = base + (ar * LDA_T + ac) * 2;
            CP16(da, ga); CP16(da + 16, ga + 8);
        }
        {
            const __nv_bfloat16* ga = gAl + (size_t)ar * K + k0 + ac;
            uint32_t da = base + A_BYTES + (ar * LDA_T + ac) * 2;
            CP16(da, ga); CP16(da + 16, ga + 8);
        }
        {
            const __nv_bfloat16* gb = gBh + (size_t)(k0 + bk) * N + bn;
            uint32_t db = base + 2 * A_BYTES + (bk * LDB_T + bn) * 2;
            CP16(db, gb); CP16(db + 16, gb + 8);
        }
        {
            const __nv_bfloat16* gb = gBl + (size_t)(k0 + bk) * N + bn;
            uint32_t db = base + 2 * A_BYTES + B_BYTES + (bk * LDB_T + bn) * 2;
            CP16(db, gb); CP16(db + 16, gb + 8);
        }
        CP_COMMIT();
    };

    issue(0);
    issue(1);

    for (int c = 0; c < nch; c++) {
        if (c + 1 < nch) CP_WAIT1();
        else             CP_WAIT0();
        __syncthreads();
        if (c + 2 < nch) issue(c + 2);

        const uint32_t base = sb + (c % 3) * BUF_BYTES;
        const uint32_t sAh = base, sAl = base + A_BYTES;
        const uint32_t sBh = base + 2 * A_BYTES, sBl = sBh + B_BYTES;

        #pragma unroll
        for (int ks = 0; ks < 2; ks++) {
            const int kb = ks * 16;
            uint32_t bh[4][2], bl[4][2];
            #pragma unroll
            for (int j = 0; j < 4; j++) {
                uint32_t boff = (uint32_t)((kb + (lane & 15)) * LDB_T
                                           + wn * 32 + j * 8) * 2;
                ldsm_x2_t(bh[j], sBh + boff);
                ldsm_x2_t(bl[j], sBl + boff);
            }
            #pragma unroll
            for (int i = 0; i < 4; i++) {
                uint32_t aoff = (uint32_t)((wm * 64 + i * 16 + (lane & 15)) * LDA_T
                                           + kb + (lane >> 4) * 8) * 2;
                uint32_t ah[4], al[4];
                ldsm_x4(ah, sAh + aoff);
                ldsm_x4(al, sAl + aoff);
                #pragma unroll
                for (int j = 0; j < 4; j++) {
                    mma_bf16(acc[i][j], ah, bh[j]);
                    mma_bf16(acc[i][j], ah, bl[j]);
                    mma_bf16(acc[i][j], al, bh[j]);
                }
            }
        }
    }

    #pragma unroll
    for (int i = 0; i < 4; i++) {
        int moff = wm * 64 + i * 16 + (lane >> 2);
        #pragma unroll
        for (int j = 0; j < 4; j++) {
            int gn = bx * 128 + wn * 32 + j * 8 + (lane & 3) * 2;
            float b0 = bias[gn], b1 = bias[gn + 1];
            #pragma unroll
            for (int half = 0; half < 2; half++) {
                int mo = moff + half * 8;
                size_t gm = aRow0 + mo;
                float v0 = acc[i][j][half * 2 + 0] + b0;
                float v1 = acc[i][j][half * 2 + 1] + b1;
                if (EPI == 1) {
                    float z0 = 0.7978845608028654f * (v0 + 0.044715f * v0 * v0 * v0);
                    float z1 = 0.7978845608028654f * (v1 + 0.044715f * v1 * v1 * v1);
                    v0 = v0 / (1.f + __expf(-2.f * z0));
                    v1 = v1 / (1.f + __expf(-2.f * z1));
                    __nv_bfloat162 lo2;
                    __nv_bfloat162 hi2 = bf2hi(v0, v1, lo2);
                    size_t o = gm * N + gn;
                    *(__nv_bfloat162*)(Chi + o) = hi2;
                    *(__nv_bfloat162*)(Clo + o) = lo2;
                } else {
                    if (EPI == 2) {
                        size_t ro = (rRow0 + mo) * N + gn;
                        v0 = resb[ro]     + gate[gn]     * v0;
                        v1 = resb[ro + 1] + gate[gn + 1] * v1;
                    }
                    *(float2*)(C + gm * N + gn) = make_float2(v0, v1);
                }
            }
        }
    }
}

// ---------------------------------------------------------------------------
// merged modulation vector (y=0: img, y=1: txt)
// ---------------------------------------------------------------------------
__global__ void k_mod2(const float* __restrict__ vec,
                       const float* __restrict__ wi, const float* __restrict__ bi,
                       const float* __restrict__ wt, const float* __restrict__ bt,
                       float* __restrict__ oi, float* __restrict__ ot)
{
    const float* w = blockIdx.y ? wt : wi;
    const float* b = blockIdx.y ? bt : bi;
    float* o       = blockIdx.y ? ot : oi;
    __shared__ float sv[HID];
    for (int i = threadIdx.x; i < HID; i += blockDim.x) {
        float x = vec[i];
        sv[i] = x / (1.f + __expf(-x));
    }
    __syncthreads();
    int j = blockIdx.x * blockDim.x + threadIdx.x;
    float a0 = 0.f, a1 = 0.f, a2 = 0.f, a3 = 0.f;
    #pragma unroll 4
    for (int i = 0; i < HID; i += 4) {
        a0 = fmaf(sv[i + 0], w[(size_t)(i + 0) * MOD6 + j], a0);
        a1 = fmaf(sv[i + 1], w[(size_t)(i + 1) * MOD6 + j], a1);
        a2 = fmaf(sv[i + 2], w[(size_t)(i + 2) * MOD6 + j], a2);
        a3 = fmaf(sv[i + 3], w[(size_t)(i + 3) * MOD6 + j], a3);
    }
    o[j] = b[j] + ((a0 + a1) + (a2 + a3));
}

// ---------------------------------------------------------------------------
// merged LN + modulation -> bf16 hi/lo
// ---------------------------------------------------------------------------
__global__ void k_ln_mod2(const float* __restrict__ in_i,
                          const float* __restrict__ in_t,
                          const float* __restrict__ sh_i,
                          const float* __restrict__ sc_i,
                          const float* __restrict__ sh_t,
                          const float* __restrict__ sc_t,
                          __nv_bfloat16* __restrict__ ohi,
                          __nv_bfloat16* __restrict__ olo)
{
    int row = blockIdx.x;
    bool isimg = (row < S_IMG);
    const float* xr = isimg ? (in_i + (size_t)row * HID)
                            : (in_t + (size_t)(row - S_IMG) * HID);
    const float* sh = isimg ? sh_i : sh_t;
    const float* sc = isimg ? sc_i : sc_t;

    float s = 0.f, s2 = 0.f;
    for (int j = threadIdx.x; j < HID; j += 256) {
        float v = xr[j];
        s += v; s2 += v * v;
    }
    #pragma unroll
    for (int off = 16; off > 0; off >>= 1) {
        s  += __shfl_xor_sync(0xffffffffu, s,  off);
        s2 += __shfl_xor_sync(0xffffffffu, s2, off);
    }
    __shared__ float rs[8], rs2[8];
    int warp = threadIdx.x >> 5, lane = threadIdx.x & 31;
    if (lane == 0) { rs[warp] = s; rs2[warp] = s2; }
    __syncthreads();
    float ts = 0.f, ts2 = 0.f;
    #pragma unroll
    for (int w = 0; w < 8; w++) { ts += rs[w]; ts2 += rs2[w]; }
    float mean = ts * (1.f / HID);
    float var  = ts2 * (1.f / HID) - mean * mean;
    float inv  = rsqrtf(var + EPS);
    size_t ro = (size_t)row * HID;
    for (int j = threadIdx.x * 2; j < HID; j += 512) {
        float v0 = (xr[j]     - mean) * inv * (1.f + sc[j])     + sh[j];
        float v1 = (xr[j + 1] - mean) * inv * (1.f + sc[j + 1]) + sh[j + 1];
        __nv_bfloat162 lo2;
        __nv_bfloat162 hi2 = bf2hi(v0, v1, lo2);
        *(__nv_bfloat162*)(ohi + ro + j) = hi2;
        *(__nv_bfloat162*)(olo + ro + j) = lo2;
    }
}

// ---------------------------------------------------------------------------
// QKV post-processing -> bf16 hi/lo q/k/v in [NH][S][HD]
// ---------------------------------------------------------------------------
__global__ void k_qkv_post(const float* __restrict__ qkv,
                           const float* __restrict__ qw_img,
                           const float* __restrict__ kw_img,
                           const float* __restrict__ qw_txt,
                           const float* __restrict__ kw_txt,
                           const float* __restrict__ cosp,
                           const float* __restrict__ sinp)
{
    int s = blockIdx.x;
    int h = blockIdx.y;
    int t = threadIdx.x;

    const float* base = qkv + (size_t)s * QKV3 + h * HD;
    float qv = base[t];
    float kv = base[HID + t];
    float vv = base[2 * HID + t];

    float sq = qv * qv, sk = kv * kv;
    #pragma unroll
    for (int off = 16; off > 0; off >>= 1) {
        sq += __shfl_xor_sync(0xffffffffu, sq, off);
        sk += __shfl_xor_sync(0xffffffffu, sk, off);
    }
    __shared__ float aq[4], ak[4];
    int warp = t >> 5, lane = t & 31;
    if (lane == 0) { aq[warp] = sq; ak[warp] = sk; }
    __syncthreads();
    float tq = aq[0] + aq[1] + aq[2] + aq[3];
    float tk = ak[0] + ak[1] + ak[2] + ak[3];
    float rq = rsqrtf(tq * (1.f / HD) + EPS);
    float rk = rsqrtf(tk * (1.f / HD) + EPS);

    bool is_img = (s < S_IMG);
    float qn = qv * rq * (is_img ? qw_img[t] : qw_txt[t]);
    float kn = kv * rk * (is_img ? kw_img[t] : kw_txt[t]);

    __shared__ float qs[HD], ks[HD];
    qs[t] = qn; ks[t] = kn;
    __syncthreads();

    if (is_img) {
        int p = t >> 1;
        float c  = cosp[(size_t)s * (HD / 2) + p];
        float sn = sinp[(size_t)s * (HD / 2) + p];
        float x1q = qs[p * 2], x2q = qs[p * 2 + 1];
        float x1k = ks[p * 2], x2k = ks[p * 2 + 1];
        if (t & 1) { qn = x2q * c + x1q * sn; kn = x2k * c + x1k * sn; }
        else       { qn = x1q * c - x2q * sn; kn = x1k * c - x2k * sn; }
    }

    size_t o = ((size_t)h * S_ALL + s) * HD + t;
    __nv_bfloat16 qh = __float2bfloat16_rn(qn);
    __nv_bfloat16 kh = __float2bfloat16_rn(kn);
    __nv_bfloat16 vh = __float2bfloat16_rn(vv);
    g_qh[o] = qh; g_ql[o] = __float2bfloat16_rn(qn - __bfloat162float(qh));
    g_kh[o] = kh; g_kl[o] = __float2bfloat16_rn(kn - __bfloat162float(kh));
    g_vh[o] = vh; g_vl[o] = __float2bfloat16_rn(vv - __bfloat162float(vh));
}

// ---------------------------------------------------------------------------
// HMMA flash attention (unchanged from R8/R12/R14 passing version)
// ---------------------------------------------------------------------------
#define LDQ 136
#define Q_BYTES2 (128 * LDQ * 2)
#define KV_ARR  (64 * LDQ * 2)
#define KV_BUF  (4 * KV_ARR)
#define ATTN_SMEM2 (2 * Q_BYTES2 + 2 * KV_BUF)

__global__ void __launch_bounds__(256, 1)
k_attn_mma(__nv_bfloat16* __restrict__ ohi, __nv_bfloat16* __restrict__ olo)
{
    extern __shared__ char smc[];
    const uint32_t sb = smem_u32(smc);
    const int tid = threadIdx.x, warp = tid >> 5, lane = tid & 31;
    const int h = blockIdx.y;
    const int q0 = blockIdx.x * 128;

    const uint32_t sQh = sb, sQl = sb + Q_BYTES2;

    {
        const __nv_bfloat16* gq = g_qh + ((size_t)h * S_ALL + q0) * HD;
        const __nv_bfloat16* gl = g_ql + ((size_t)h * S_ALL + q0) * HD;
        #pragma unroll
        for (int it = 0; it < 8; it++) {
            int idx = tid + it * 256;
            int row = idx >> 4, c = idx & 15;
            uint32_t dst = (uint32_t)(row * LDQ + c * 8) * 2;
            CP16(sQh + dst, gq + (size_t)row * HD + c * 8);
            CP16(sQl + dst, gl + (size_t)row * HD + c * 8);
        }
        CP_COMMIT();
    }

    auto issue_kv = [&](int t) {
        const uint32_t kb = sb + 2 * Q_BYTES2 + (t & 1) * KV_BUF;
        const size_t src0 = ((size_t)h * S_ALL + t * 64) * HD;
        #pragma unroll
        for (int it = 0; it < 4; it++) {
            int idx = tid + it * 256;
            int row = idx >> 4, c = idx & 15;
            size_t so = src0 + (size_t)row * HD + c * 8;
            uint32_t dst = kb + (uint32_t)(row * LDQ + c * 8) * 2;
            CP16(dst,              g_kh + so);
            CP16(dst + KV_ARR,     g_kl + so);
            CP16(dst + 2 * KV_ARR, g_vh + so);
            CP16(dst + 3 * KV_ARR, g_vl + so);
        }
        CP_COMMIT();
    };

    issue_kv(0);
    CP_WAIT0();
    __syncthreads();

    float oacc[16][4];
    #pragma unroll
    for (int j = 0; j < 16; j++)
        #pragma unroll
        for (int r = 0; r < 4; r++) oacc[j][r] = 0.f;
    float m0 = -1e30f, m1 = -1e30f, l0 = 0.f, l1 = 0.f;
    const float scale = 0.08838834764831845f;

    const int lrow = lane & 15;
    const int lkh  = lane >> 4;
    const int btn  = lane & 7;
    const int btk  = (lane >> 3) & 1;

    for (int t = 0; t < 36; t++) {
        if (t + 1 < 36) issue_kv(t + 1);

        const uint32_t kb  = sb + 2 * Q_BYTES2 + (t & 1) * KV_BUF;
        const uint32_t sKh = kb, sKl = kb + KV_ARR;
        const uint32_t sVh = kb + 2 * KV_ARR, sVl = kb + 3 * KV_ARR;

        float sacc[8][4];
        #pragma unroll
        for (int j = 0; j < 8; j++)
            #pragma unroll
            for (int r = 0; r < 4; r++) sacc[j][r] = 0.f;

        #pragma unroll
        for (int ks = 0; ks < 8; ks++) {
            const int kbft = ks * 16;
            uint32_t qh4[4], ql4[4];
            uint32_t aoff = (uint32_t)((warp * 16 + lrow) * LDQ + kbft + lkh * 8) * 2;
            ldsm_x4(qh4, sQh + aoff);
            ldsm_x4(ql4, sQl + aoff);
            #pragma unroll
            for (int j = 0; j < 8; j++) {
                uint32_t kh2[2], kl2[2];
                uint32_t boff = (uint32_t)((j * 8 + btn) * LDQ + kbft + btk * 8) * 2;
                ldsm_x2(kh2, sKh + boff);
                ldsm_x2(kl2, sKl + boff);
                mma_bf16(sacc[j], qh4, kh2);
                mma_bf16(sacc[j], qh4, kl2);
                mma_bf16(sacc[j], ql4, kh2);
            }
        }

        float mr0 = -1e30f, mr1 = -1e30f;
        #pragma unroll
        for (int j = 0; j < 8; j++) {
            sacc[j][0] *= scale; sacc[j][1] *= scale;
            sacc[j][2] *= scale; sacc[j][3] *= scale;
            mr0 = fmaxf(mr0, fmaxf(sacc[j][0], sacc[j][1]));
            mr1 = fmaxf(mr1, fmaxf(sacc[j][2], sacc[j][3]));
        }
        mr0 = fmaxf(mr0, __shfl_xor_sync(0xffffffffu, mr0, 1));
        mr0 = fmaxf(mr0, __shfl_xor_sync(0xffffffffu, mr0, 2));
        mr1 = fmaxf(mr1, __shfl_xor_sync(0xffffffffu, mr1, 1));
        mr1 = fmaxf(mr1, __shfl_xor_sync(0xffffffffu, mr1, 2));
        float mn0 = fmaxf(m0, mr0), mn1 = fmaxf(m1, mr1);
        float a0 = __expf(m0 - mn0), a1 = __expf(m1 - mn1);
        m0 = mn0; m1 = mn1;

        float rs0 = 0.f, rs1 = 0.f;
        #pragma unroll
        for (int j = 0; j < 8; j++) {
            sacc[j][0] = __expf(sacc[j][0] - mn0);
            sacc[j][1] = __expf(sacc[j][1] - mn0);
            sacc[j][2] = __expf(sacc[j][2] - mn1);
            sacc[j][3] = __expf(sacc[j][3] - mn1);
            rs0 += sacc[j][0] + sacc[j][1];
            rs1 += sacc[j][2] + sacc[j][3];
        }
        rs0 += __shfl_xor_sync(0xffffffffu, rs0, 1);
        rs0 += __shfl_xor_sync(0xffffffffu, rs0, 2);
        rs1 += __shfl_xor_sync(0xffffffffu, rs1, 1);
        rs1 += __shfl_xor_sync(0xffffffffu, rs1, 2);
        l0 = l0 * a0 + rs0;
        l1 = l1 * a1 + rs1;

        uint32_t phi[4][4], plo[4][4];
        #pragma unroll
        for (int tt = 0; tt < 4; tt++) {
            __nv_bfloat162 lo2;
            __nv_bfloat162 hi2;
            hi2 = bf2hi(sacc[2*tt][0],   sacc[2*tt][1],   lo2);
            phi[tt][0] = *(uint32_t*)&hi2; plo[tt][0] = *(uint32_t*)&lo2;
            hi2 = bf2hi(sacc[2*tt][2],   sacc[2*tt][3],   lo2);
            phi[tt][1] = *(uint32_t*)&hi2; plo[tt][1] = *(uint32_t*)&lo2;
            hi2 = bf2hi(sacc[2*tt+1][0], sacc[2*tt+1][1], lo2);
            phi[tt][2] = *(uint32_t*)&hi2; plo[tt][2] = *(uint32_t*)&lo2;
            hi2 = bf2hi(sacc[2*tt+1][2], sacc[2*tt+1][3], lo2);
            phi[tt][3] = *(uint32_t*)&hi2; plo[tt][3] = *(uint32_t*)&lo2;
        }

        #pragma unroll
        for (int j = 0; j < 16; j++) {
            oacc[j][0] *= a0; oacc[j][1] *= a0;
            oacc[j][2] *= a1; oacc[j][3] *= a1;
        }

        #pragma unroll
        for (int tt = 0; tt < 4; tt++) {
            #pragma unroll
            for (int j = 0; j < 16; j++) {
                uint32_t vh2[2], vl2[2];
                uint32_t boff = (uint32_t)((tt * 16 + lrow) * LDQ + j * 8) * 2;
                ldsm_x2_t(vh2, sVh + boff);
                ldsm_x2_t(vl2, sVl + boff);
                mma_bf16(oacc[j], phi[tt], vh2);
                mma_bf16(oacc[j], plo[tt], vh2);
                mma_bf16(oacc[j], phi[tt], vl2);
            }
        }

        if (t + 1 < 36) CP_WAIT0();
        __syncthreads();
    }

    float inv0 = 1.f / l0, inv1 = 1.f / l1;
    int r0 = q0 + warp * 16 + (lane >> 2);
    int r1 = r0 + 8;
    #pragma unroll
    for (int j = 0; j < 16; j++) {
        int col = h * HD + j * 8 + (lane & 3) * 2;
        __nv_bfloat162 lo2;
        __nv_bfloat162 hi2 = bf2hi(oacc[j][0] * inv0, oacc[j][1] * inv0, lo2);
        size_t o0 = (size_t)r0 * HID + col;
        *(__nv_bfloat162*)(ohi + o0) = hi2;
        *(__nv_bfloat162*)(olo + o0) = lo2;
        hi2 = bf2hi(oacc[j][2] * inv1, oacc[j][3] * inv1, lo2);
        size_t o1 = (size_t)r1 * HID + col;
        *(__nv_bfloat162*)(ohi + o1) = hi2;
        *(__nv_bfloat162*)(olo + o1) = lo2;
    }
}

// ---------------------------------------------------------------------------
// launch
// ---------------------------------------------------------------------------
extern "C" void kernel_launch(void* const* d_in, const int* in_sizes, int n_in,
                              void* d_out, int out_size)
{
    const float* img        = (const float*)d_in[0];
    const float* txt        = (const float*)d_in[1];
    const float* vec        = (const float*)d_in[2];
    const float* cosp       = (const float*)d_in[3];
    const float* sinp       = (const float*)d_in[4];
    const float* img_mod_w  = (const float*)d_in[5];
    const float* img_mod_b  = (const float*)d_in[6];
    const float* img_qkv_w  = (const float*)d_in[7];
    const float* img_qkv_b  = (const float*)d_in[8];
    const float* img_qn_w   = (const float*)d_in[9];
    const float* img_kn_w   = (const float*)d_in[10];
    const float* img_proj_w = (const float*)d_in[11];
    const float* img_proj_b = (const float*)d_in[12];
    const float* img_mlp_w1 = (const float*)d_in[13];
    const float* img_mlp_b1 = (const float*)d_in[14];
    const float* img_mlp_w2 = (const float*)d_in[15];
    const float* img_mlp_b2 = (const float*)d_in[16];
    const float* txt_mod_w  = (const float*)d_in[17];
    const float* txt_mod_b  = (const float*)d_in[18];
    const float* txt_qkv_w  = (const float*)d_in[19];
    const float* txt_qkv_b  = (const float*)d_in[20];
    const float* txt_qn_w   = (const float*)d_in[21];
    const float* txt_kn_w   = (const float*)d_in[22];
    const float* txt_proj_w = (const float*)d_in[23];
    const float* txt_proj_b = (const float*)d_in[24];
    const float* txt_mlp_w1 = (const float*)d_in[25];
    const float* txt_mlp_b1 = (const float*)d_in[26];
    const float* txt_mlp_w2 = (const float*)d_in[27];
    const float* txt_mlp_b2 = (const float*)d_in[28];
    float* out = (float*)d_out;

    float *mod_i, *mod_t, *qkv, *res;
    __nv_bfloat16 *xh, *xl, *x2h, *x2l, *ath, *atl, *hh, *hl;
    __nv_bfloat16 *wiq_h, *wiq_l, *wip_h, *wip_l, *wi1_h, *wi1_l, *wi2_h, *wi2_l;
    __nv_bfloat16 *wtq_h, *wtq_l, *wtp_h, *wtp_l, *wt1_h, *wt1_l, *wt2_h, *wt2_l;

    cudaGetSymbolAddress((void**)&mod_i, g_mod_i);
    cudaGetSymbolAddress((void**)&mod_t, g_mod_t);
    cudaGetSymbolAddress((void**)&qkv,   g_qkv);
    cudaGetSymbolAddress((void**)&res,   g_res);
    cudaGetSymbolAddress((void**)&xh,  g_xln_h);  cudaGetSymbolAddress((void**)&xl,  g_xln_l);
    cudaGetSymbolAddress((void**)&x2h, g_x2_h);   cudaGetSymbolAddress((void**)&x2l, g_x2_l);
    cudaGetSymbolAddress((void**)&ath, g_at_h);   cudaGetSymbolAddress((void**)&atl, g_at_l);
    cudaGetSymbolAddress((void**)&hh,  g_hh);     cudaGetSymbolAddress((void**)&hl,  g_hl);
    cudaGetSymbolAddress((void**)&wiq_h, g_wiqkv_h); cudaGetSymbolAddress((void**)&wiq_l, g_wiqkv_l);
    cudaGetSymbolAddress((void**)&wip_h, g_wipro_h); cudaGetSymbolAddress((void**)&wip_l, g_wipro_l);
    cudaGetSymbolAddress((void**)&wi1_h, g_wiw1_h);  cudaGetSymbolAddress((void**)&wi1_l, g_wiw1_l);
    cudaGetSymbolAddress((void**)&wi2_h, g_wiw2_h);  cudaGetSymbolAddress((void**)&wi2_l, g_wiw2_l);
    cudaGetSymbolAddress((void**)&wtq_h, g_wtqkv_h); cudaGetSymbolAddress((void**)&wtq_l, g_wtqkv_l);
    cudaGetSymbolAddress((void**)&wtp_h, g_wtpro_h); cudaGetSymbolAddress((void**)&wtp_l, g_wtpro_l);
    cudaGetSymbolAddress((void**)&wt1_h, g_wtw1_h);  cudaGetSymbolAddress((void**)&wt1_l, g_wtw1_l);
    cudaGetSymbolAddress((void**)&wt2_h, g_wtw2_h);  cudaGetSymbolAddress((void**)&wt2_l, g_wtw2_l);

    cudaFuncSetAttribute(k_attn_mma, cudaFuncAttributeMaxDynamicSharedMemorySize,
                         (int)ATTN_SMEM2);
    cudaFuncSetAttribute(k_gemm2<0>, cudaFuncAttributeMaxDynamicSharedMemorySize, GEMM_SMEM);
    cudaFuncSetAttribute(k_gemm2<1>, cudaFuncAttributeMaxDynamicSharedMemorySize, GEMM_SMEM);
    cudaFuncSetAttribute(k_gemm2<2>, cudaFuncAttributeMaxDynamicSharedMemorySize, GEMM_SMEM);

    // prologue: weight splits + modulation + LN
    k_split4b<<<dim3((HID * QKV3) / 1024, 2), 256>>>(
        (const float4*)img_qkv_w, (__nv_bfloat162*)wiq_h, (__nv_bfloat162*)wiq_l,
        (const float4*)txt_qkv_w, (__nv_bfloat162*)wtq_h, (__nv_bfloat162*)wtq_l);
    k_mod2<<<dim3(MOD6 / 256, 2), 256>>>(vec, img_mod_w, img_mod_b,
                                         txt_mod_w, txt_mod_b, mod_i, mod_t);
    k_ln_mod2<<<S_ALL, 256>>>(img, txt, mod_i, mod_i + HID,
                              mod_t, mod_t + HID, xh, xl);
    k_split4b<<<dim3((HID * HID) / 1024, 2), 256>>>(
        (const float4*)img_proj_w, (__nv_bfloat162*)wip_h, (__nv_bfloat162*)wip_l,
        (const float4*)txt_proj_w, (__nv_bfloat162*)wtp_h, (__nv_bfloat162*)wtp_l);
    k_split4b<<<dim3((HID * MLPD) / 1024, 2), 256>>>(
        (const float4*)img_mlp_w1, (__nv_bfloat162*)wi1_h, (__nv_bfloat162*)wi1_l,
        (const float4*)txt_mlp_w1, (__nv_bfloat162*)wt1_h, (__nv_bfloat162*)wt1_l);

    // merged QKV GEMM (grid: x = M-blocks, y = N-strips)
    k_gemm2<0><<<dim3(MBALL, QKV3 / 128), 256, GEMM_SMEM>>>(
        xh, xl, wiq_h, wiq_l, wtq_h, wtq_l, img_qkv_b, txt_qkv_b,
        nullptr, nullptr, nullptr, nullptr, qkv, nullptr, nullptr,
        QKV3, HID);

    k_split4b<<<dim3((HID * MLPD) / 1024, 2), 256>>>(
        (const float4*)img_mlp_w2, (__nv_bfloat162*)wi2_h, (__nv_bfloat162*)wi2_l,
        (const float4*)txt_mlp_w2, (__nv_bfloat162*)wt2_h, (__nv_bfloat162*)wt2_l);

    // rms-norm + rope + scatter
    k_qkv_post<<<dim3(S_ALL, NH), HD>>>(qkv, img_qn_w, img_kn_w,
                                        txt_qn_w, txt_kn_w, cosp, sinp);

    // attention
    k_attn_mma<<<dim3(S_ALL / 128, NH), 256, ATTN_SMEM2>>>(ath, atl);

    // output projection + gated residual
    k_gemm2<2><<<dim3(MBALL, HID / 128), 256, GEMM_SMEM>>>(
        ath, atl, wip_h, wip_l, wtp_h, wtp_l, img_proj_b, txt_proj_b,
        img, txt, mod_i + 2 * HID, mod_t + 2 * HID, res, nullptr, nullptr,
        HID, HID);

    // LN + mlp modulation
    k_ln_mod2<<<S_ALL, 256>>>(res, res + IMGOFF, mod_i + 3 * HID,
                              mod_i + 4 * HID, mod_t + 3 * HID,
                              mod_t + 4 * HID, x2h, x2l);

    // MLP up + gelu
    k_gemm2<1><<<dim3(MBALL, MLPD / 128), 256, GEMM_SMEM>>>(
        x2h, x2l, wi1_h, wi1_l, wt1_h, wt1_l, img_mlp_b1, txt_mlp_b1,
        nullptr, nullptr, nullptr, nullptr, nullptr, hh, hl,
        MLPD, HID);

    // MLP down + gated residual -> final output
    k_gemm2<2><<<dim3(MBALL, HID / 128), 256, GEMM_SMEM>>>(
        hh, hl, wi2_h, wi2_l, wt2_h, wt2_l, img_mlp_b2, txt_mlp_b2,
        res, res + IMGOFF, mod_i + 5 * HID, mod_t + 5 * HID, out,
        nullptr, nullptr, HID, MLPD);
}

// round 17
// speedup vs baseline: 1.5257x; 1.5257x over previous
#include <cuda_runtime.h>
#include <cuda_bf16.h>
#include <math.h>
#include <cstdint>

// ---------------------------------------------------------------------------
// Problem constants
// ---------------------------------------------------------------------------
#define S_IMG 2048
#define S_TXT 256
#define S_ALL 2304
#define HID   3072
#define NH    24
#define HD    128
#define MLPD  12288
#define QKV3  9216
#define MOD6  18432
#define EPS   1e-6f
#define IMGOFF ((size_t)S_IMG * HID)
#define MBI   (S_IMG / 128)
#define MBALL (S_ALL / 128)

// ---------------------------------------------------------------------------
// Static scratch
// ---------------------------------------------------------------------------
__device__ float g_mod_i[MOD6];
__device__ float g_mod_t[MOD6];
__device__ float g_qkv [(size_t)S_ALL * QKV3];
__device__ float g_res [(size_t)S_ALL * HID];

__device__ __align__(16) __nv_bfloat16 g_qh[(size_t)NH * S_ALL * HD];
__device__ __align__(16) __nv_bfloat16 g_ql[(size_t)NH * S_ALL * HD];
__device__ __align__(16) __nv_bfloat16 g_kh[(size_t)NH * S_ALL * HD];
__device__ __align__(16) __nv_bfloat16 g_kl[(size_t)NH * S_ALL * HD];
__device__ __align__(16) __nv_bfloat16 g_vh[(size_t)NH * S_ALL * HD];
__device__ __align__(16) __nv_bfloat16 g_vl[(size_t)NH * S_ALL * HD];

__device__ __align__(16) __nv_bfloat16 g_xln_h[(size_t)S_ALL * HID];
__device__ __align__(16) __nv_bfloat16 g_xln_l[(size_t)S_ALL * HID];
__device__ __align__(16) __nv_bfloat16 g_x2_h [(size_t)S_ALL * HID];
__device__ __align__(16) __nv_bfloat16 g_x2_l [(size_t)S_ALL * HID];
__device__ __align__(16) __nv_bfloat16 g_at_h [(size_t)S_ALL * HID];
__device__ __align__(16) __nv_bfloat16 g_at_l [(size_t)S_ALL * HID];
__device__ __align__(16) __nv_bfloat16 g_hh   [(size_t)S_ALL * MLPD];
__device__ __align__(16) __nv_bfloat16 g_hl   [(size_t)S_ALL * MLPD];

__device__ __align__(16) __nv_bfloat16 g_wiqkv_h[(size_t)HID * QKV3];
__device__ __align__(16) __nv_bfloat16 g_wiqkv_l[(size_t)HID * QKV3];
__device__ __align__(16) __nv_bfloat16 g_wipro_h[(size_t)HID * HID];
__device__ __align__(16) __nv_bfloat16 g_wipro_l[(size_t)HID * HID];
__device__ __align__(16) __nv_bfloat16 g_wiw1_h [(size_t)HID * MLPD];
__device__ __align__(16) __nv_bfloat16 g_wiw1_l [(size_t)HID * MLPD];
__device__ __align__(16) __nv_bfloat16 g_wiw2_h [(size_t)MLPD * HID];
__device__ __align__(16) __nv_bfloat16 g_wiw2_l [(size_t)MLPD * HID];
__device__ __align__(16) __nv_bfloat16 g_wtqkv_h[(size_t)HID * QKV3];
__device__ __align__(16) __nv_bfloat16 g_wtqkv_l[(size_t)HID * QKV3];
__device__ __align__(16) __nv_bfloat16 g_wtpro_h[(size_t)HID * HID];
__device__ __align__(16) __nv_bfloat16 g_wtpro_l[(size_t)HID * HID];
__device__ __align__(16) __nv_bfloat16 g_wtw1_h [(size_t)HID * MLPD];
__device__ __align__(16) __nv_bfloat16 g_wtw1_l [(size_t)HID * MLPD];
__device__ __align__(16) __nv_bfloat16 g_wtw2_h [(size_t)MLPD * HID];
__device__ __align__(16) __nv_bfloat16 g_wtw2_l [(size_t)MLPD * HID];

// ---------------------------------------------------------------------------
// PTX helpers
// ---------------------------------------------------------------------------
__device__ __forceinline__ uint32_t smem_u32(const void* p) {
    uint32_t a;
    asm("{ .reg .u64 t; cvta.to.shared.u64 t, %1; cvt.u32.u64 %0, t; }"
        : "=r"(a) : "l"(p));
    return a;
}
__device__ __forceinline__ void ldsm_x4(uint32_t* r, uint32_t addr) {
    asm volatile("ldmatrix.sync.aligned.m8n8.x4.shared.b16 {%0,%1,%2,%3}, [%4];"
        : "=r"(r[0]), "=r"(r[1]), "=r"(r[2]), "=r"(r[3]) : "r"(addr));
}
__device__ __forceinline__ void ldsm_x2(uint32_t* r, uint32_t addr) {
    asm volatile("ldmatrix.sync.aligned.m8n8.x2.shared.b16 {%0,%1}, [%2];"
        : "=r"(r[0]), "=r"(r[1]) : "r"(addr));
}
__device__ __forceinline__ void ldsm_x2_t(uint32_t* r, uint32_t addr) {
    asm volatile("ldmatrix.sync.aligned.m8n8.x2.trans.shared.b16 {%0,%1}, [%2];"
        : "=r"(r[0]), "=r"(r[1]) : "r"(addr));
}
__device__ __forceinline__ void mma_bf16(float* d, const uint32_t* a,
                                         const uint32_t* b) {
    asm volatile("mma.sync.aligned.m16n8k16.row.col.f32.bf16.bf16.f32 "
        "{%0,%1,%2,%3}, {%4,%5,%6,%7}, {%8,%9}, {%0,%1,%2,%3};"
        : "+f"(d[0]), "+f"(d[1]), "+f"(d[2]), "+f"(d[3])
        : "r"(a[0]), "r"(a[1]), "r"(a[2]), "r"(a[3]), "r"(b[0]), "r"(b[1]));
}
#define CP16(dst, src) \
    asm volatile("cp.async.cg.shared.global [%0], [%1], 16;" \
                 :: "r"(dst), "l"(src))
#define CP_COMMIT() asm volatile("cp.async.commit_group;" ::: "memory")
#define CP_WAIT1()  asm volatile("cp.async.wait_group 1;" ::: "memory")
#define CP_WAIT0()  asm volatile("cp.async.wait_group 0;" ::: "memory")

__device__ __forceinline__ __nv_bfloat162 bf2hi(float a, float b,
                                                __nv_bfloat162& lo) {
    __nv_bfloat16 ha = __float2bfloat16_rn(a);
    __nv_bfloat16 hb = __float2bfloat16_rn(b);
    lo.x = __float2bfloat16_rn(a - __bfloat162float(ha));
    lo.y = __float2bfloat16_rn(b - __bfloat162float(hb));
    __nv_bfloat16 h2x = ha;
    __nv_bfloat162 h; h.x = h2x; h.y = hb;
    return h;
}
__device__ __forceinline__ uint32_t u32of(__nv_bfloat162 v) {
    return *(uint32_t*)&v;
}

// ---------------------------------------------------------------------------
// weight split (paired img/txt via grid.y), 8 floats/thread, 16B stores
// ---------------------------------------------------------------------------
__global__ void k_split4b(const float4* __restrict__ wi,
                          uint4* __restrict__ hi_i,
                          uint4* __restrict__ lo_i,
                          const float4* __restrict__ wt,
                          uint4* __restrict__ hi_t,
                          uint4* __restrict__ lo_t)
{
    const float4* w = blockIdx.y ? wt : wi;
    uint4* hi = blockIdx.y ? hi_t : hi_i;
    uint4* lo = blockIdx.y ? lo_t : lo_i;
    int i = blockIdx.x * 256 + threadIdx.x;
    float4 a = w[2 * i];
    float4 b = w[2 * i + 1];
    __nv_bfloat162 l0, l1, l2, l3;
    __nv_bfloat162 h0 = bf2hi(a.x, a.y, l0);
    __nv_bfloat162 h1 = bf2hi(a.z, a.w, l1);
    __nv_bfloat162 h2 = bf2hi(b.x, b.y, l2);
    __nv_bfloat162 h3 = bf2hi(b.z, b.w, l3);
    hi[i] = make_uint4(u32of(h0), u32of(h1), u32of(h2), u32of(h3));
    lo[i] = make_uint4(u32of(l0), u32of(l1), u32of(l2), u32of(l3));
}

// ---------------------------------------------------------------------------
// merged split-bf16 HMMA GEMM (R12/R14-passing version; grid x=N, y=M)
// EPI: 0 bias->fp32; 1 bias+gelu->bf16 hi/lo; 2 res+gate*(acc+bias)->fp32
// ---------------------------------------------------------------------------
#define LDA_T 40
#define LDB_T 136
#define A_BYTES (128 * LDA_T * 2)
#define B_BYTES (32 * LDB_T * 2)
#define BUF_BYTES (2 * A_BYTES + 2 * B_BYTES)   // 37888
#define GEMM_SMEM (3 * BUF_BYTES)               // 113664

template<int EPI>
__global__ void __launch_bounds__(256, 2)
k_gemm2(const __nv_bfloat16* __restrict__ Ahi,
        const __nv_bfloat16* __restrict__ Alo,
        const __nv_bfloat16* __restrict__ Bhi_i,
        const __nv_bfloat16* __restrict__ Bli_i,
        const __nv_bfloat16* __restrict__ Bhi_t,
        const __nv_bfloat16* __restrict__ Bli_t,
        const float* __restrict__ bias_i, const float* __restrict__ bias_t,
        const float* __restrict__ res_i,  const float* __restrict__ res_t,
        const float* __restrict__ gate_i, const float* __restrict__ gate_t,
        float* __restrict__ C,
        __nv_bfloat16* __restrict__ Chi, __nv_bfloat16* __restrict__ Clo,
        int N, int K)
{
    extern __shared__ char smc[];
    const uint32_t sb = smem_u32(smc);
    const int tid = threadIdx.x, warp = tid >> 5, lane = tid & 31;
    const int wm = warp & 1, wn = warp >> 1;
    const int bx = blockIdx.x, by = blockIdx.y;
    const int nch = K >> 5;

    const bool isimg = (by < MBI);
    const __nv_bfloat16* Bh = isimg ? Bhi_i : Bhi_t;
    const __nv_bfloat16* Bl = isimg ? Bli_i : Bli_t;
    const float* bias = isimg ? bias_i : bias_t;
    const float* resb = isimg ? res_i  : res_t;
    const float* gate = isimg ? gate_i : gate_t;
    const size_t aRow0 = (size_t)by * 128;
    const size_t rRow0 = isimg ? aRow0 : (size_t)(by - MBI) * 128;

    const __nv_bfloat16* gAh = Ahi + aRow0 * K;
    const __nv_bfloat16* gAl = Alo + aRow0 * K;
    const __nv_bfloat16* gBh = Bh + bx * 128;
    const __nv_bfloat16* gBl = Bl + bx * 128;

    const int ar = tid >> 1;
    const int ac = (tid & 1) * 16;
    const int bk = tid >> 3;
    const int bn = (tid & 7) * 16;

    float acc[4][4][4];
    #pragma unroll
    for (int i = 0; i < 4; i++)
        #pragma unroll
        for (int j = 0; j < 4; j++)
            #pragma unroll
            for (int r = 0; r < 4; r++) acc[i][j][r] = 0.f;

    auto issue = [&](int c) {
        const int k0 = c << 5;
        const uint32_t base = sb + (c % 3) * BUF_BYTES;
        {
            const __nv_bfloat16* ga = gAh + (size_t)ar * K + k0 + ac;
            uint32_t da = base + (ar * LDA_T + ac) * 2;
            CP16(da, ga); CP16(da + 16, ga + 8);
        }
        {
            const __nv_bfloat16* ga = gAl + (size_t)ar * K + k0 + ac;
            uint32_t da = base + A_BYTES + (ar * LDA_T + ac) * 2;
            CP16(da, ga); CP16(da + 16, ga + 8);
        }
        {
            const __nv_bfloat16* gb = gBh + (size_t)(k0 + bk) * N + bn;
            uint32_t db = base + 2 * A_BYTES + (bk * LDB_T + bn) * 2;
            CP16(db, gb); CP16(db + 16, gb + 8);
        }
        {
            const __nv_bfloat16* gb = gBl + (size_t)(k0 + bk) * N + bn;
            uint32_t db = base + 2 * A_BYTES + B_BYTES + (bk * LDB_T + bn) * 2;
            CP16(db, gb); CP16(db + 16, gb + 8);
        }
        CP_COMMIT();
    };

    issue(0);
    issue(1);

    for (int c = 0; c < nch; c++) {
        if (c + 1 < nch) CP_WAIT1();
        else             CP_WAIT0();
        __syncthreads();
        if (c + 2 < nch) issue(c + 2);

        const uint32_t base = sb + (c % 3) * BUF_BYTES;
        const uint32_t sAh = base, sAl = base + A_BYTES;
        const uint32_t sBh = base + 2 * A_BYTES, sBl = sBh + B_BYTES;

        #pragma unroll
        for (int ks = 0; ks < 2; ks++) {
            const int kb = ks * 16;
            uint32_t bh[4][2], bl[4][2];
            #pragma unroll
            for (int j = 0; j < 4; j++) {
                uint32_t boff = (uint32_t)((kb + (lane & 15)) * LDB_T
                                           + wn * 32 + j * 8) * 2;
                ldsm_x2_t(bh[j], sBh + boff);
                ldsm_x2_t(bl[j], sBl + boff);
            }
            #pragma unroll
            for (int i = 0; i < 4; i++) {
                uint32_t aoff = (uint32_t)((wm * 64 + i * 16 + (lane & 15)) * LDA_T
                                           + kb + (lane >> 4) * 8) * 2;
                uint32_t ah[4], al[4];
                ldsm_x4(ah, sAh + aoff);
                ldsm_x4(al, sAl + aoff);
                #pragma unroll
                for (int j = 0; j < 4; j++) {
                    mma_bf16(acc[i][j], ah, bh[j]);
                    mma_bf16(acc[i][j], ah, bl[j]);
                    mma_bf16(acc[i][j], al, bh[j]);
                }
            }
        }
    }

    #pragma unroll
    for (int i = 0; i < 4; i++) {
        int moff = wm * 64 + i * 16 + (lane >> 2);
        #pragma unroll
        for (int j = 0; j < 4; j++) {
            int gn = bx * 128 + wn * 32 + j * 8 + (lane & 3) * 2;
            float b0 = bias[gn], b1 = bias[gn + 1];
            #pragma unroll
            for (int half = 0; half < 2; half++) {
                int mo = moff + half * 8;
                size_t gm = aRow0 + mo;
                float v0 = acc[i][j][half * 2 + 0] + b0;
                float v1 = acc[i][j][half * 2 + 1] + b1;
                if (EPI == 1) {
                    float z0 = 0.7978845608028654f * (v0 + 0.044715f * v0 * v0 * v0);
                    float z1 = 0.7978845608028654f * (v1 + 0.044715f * v1 * v1 * v1);
                    v0 = v0 / (1.f + __expf(-2.f * z0));
                    v1 = v1 / (1.f + __expf(-2.f * z1));
                    __nv_bfloat162 lo2;
                    __nv_bfloat162 hi2 = bf2hi(v0, v1, lo2);
                    size_t o = gm * N + gn;
                    *(__nv_bfloat162*)(Chi + o) = hi2;
                    *(__nv_bfloat162*)(Clo + o) = lo2;
                } else {
                    if (EPI == 2) {
                        size_t ro = (rRow0 + mo) * N + gn;
                        v0 = resb[ro]     + gate[gn]     * v0;
                        v1 = resb[ro + 1] + gate[gn + 1] * v1;
                    }
                    *(float2*)(C + gm * N + gn) = make_float2(v0, v1);
                }
            }
        }
    }
}

// ---------------------------------------------------------------------------
// merged modulation vector (y=0: img, y=1: txt)
// ---------------------------------------------------------------------------
__global__ void k_mod2(const float* __restrict__ vec,
                       const float* __restrict__ wi, const float* __restrict__ bi,
                       const float* __restrict__ wt, const float* __restrict__ bt,
                       float* __restrict__ oi, float* __restrict__ ot)
{
    const float* w = blockIdx.y ? wt : wi;
    const float* b = blockIdx.y ? bt : bi;
    float* o       = blockIdx.y ? ot : oi;
    __shared__ float sv[HID];
    for (int i = threadIdx.x; i < HID; i += blockDim.x) {
        float x = vec[i];
        sv[i] = x / (1.f + __expf(-x));
    }
    __syncthreads();
    int j = blockIdx.x * blockDim.x + threadIdx.x;
    float a0 = 0.f, a1 = 0.f, a2 = 0.f, a3 = 0.f;
    #pragma unroll 4
    for (int i = 0; i < HID; i += 4) {
        a0 = fmaf(sv[i + 0], w[(size_t)(i + 0) * MOD6 + j], a0);
        a1 = fmaf(sv[i + 1], w[(size_t)(i + 1) * MOD6 + j], a1);
        a2 = fmaf(sv[i + 2], w[(size_t)(i + 2) * MOD6 + j], a2);
        a3 = fmaf(sv[i + 3], w[(size_t)(i + 3) * MOD6 + j], a3);
    }
    o[j] = b[j] + ((a0 + a1) + (a2 + a3));
}

// ---------------------------------------------------------------------------
// merged LN + modulation -> bf16 hi/lo
// ---------------------------------------------------------------------------
__global__ void k_ln_mod2(const float* __restrict__ in_i,
                          const float* __restrict__ in_t,
                          const float* __restrict__ sh_i,
                          const float* __restrict__ sc_i,
                          const float* __restrict__ sh_t,
                          const float* __restrict__ sc_t,
                          __nv_bfloat16* __restrict__ ohi,
                          __nv_bfloat16* __restrict__ olo)
{
    int row = blockIdx.x;
    bool isimg = (row < S_IMG);
    const float* xr = isimg ? (in_i + (size_t)row * HID)
                            : (in_t + (size_t)(row - S_IMG) * HID);
    const float* sh = isimg ? sh_i : sh_t;
    const float* sc = isimg ? sc_i : sc_t;

    float s = 0.f, s2 = 0.f;
    for (int j = threadIdx.x; j < HID; j += 256) {
        float v = xr[j];
        s += v; s2 += v * v;
    }
    #pragma unroll
    for (int off = 16; off > 0; off >>= 1) {
        s  += __shfl_xor_sync(0xffffffffu, s,  off);
        s2 += __shfl_xor_sync(0xffffffffu, s2, off);
    }
    __shared__ float rs[8], rs2[8];
    int warp = threadIdx.x >> 5, lane = threadIdx.x & 31;
    if (lane == 0) { rs[warp] = s; rs2[warp] = s2; }
    __syncthreads();
    float ts = 0.f, ts2 = 0.f;
    #pragma unroll
    for (int w = 0; w < 8; w++) { ts += rs[w]; ts2 += rs2[w]; }
    float mean = ts * (1.f / HID);
    float var  = ts2 * (1.f / HID) - mean * mean;
    float inv  = rsqrtf(var + EPS);
    size_t ro = (size_t)row * HID;
    for (int j = threadIdx.x * 2; j < HID; j += 512) {
        float v0 = (xr[j]     - mean) * inv * (1.f + sc[j])     + sh[j];
        float v1 = (xr[j + 1] - mean) * inv * (1.f + sc[j + 1]) + sh[j + 1];
        __nv_bfloat162 lo2;
        __nv_bfloat162 hi2 = bf2hi(v0, v1, lo2);
        *(__nv_bfloat162*)(ohi + ro + j) = hi2;
        *(__nv_bfloat162*)(olo + ro + j) = lo2;
    }
}

// ---------------------------------------------------------------------------
// QKV post-processing -> bf16 hi/lo q/k/v in [NH][S][HD]
// ---------------------------------------------------------------------------
__global__ void k_qkv_post(const float* __restrict__ qkv,
                           const float* __restrict__ qw_img,
                           const float* __restrict__ kw_img,
                           const float* __restrict__ qw_txt,
                           const float* __restrict__ kw_txt,
                           const float* __restrict__ cosp,
                           const float* __restrict__ sinp)
{
    int s = blockIdx.x;
    int h = blockIdx.y;
    int t = threadIdx.x;

    const float* base = qkv + (size_t)s * QKV3 + h * HD;
    float qv = base[t];
    float kv = base[HID + t];
    float vv = base[2 * HID + t];

    float sq = qv * qv, sk = kv * kv;
    #pragma unroll
    for (int off = 16; off > 0; off >>= 1) {
        sq += __shfl_xor_sync(0xffffffffu, sq, off);
        sk += __shfl_xor_sync(0xffffffffu, sk, off);
    }
    __shared__ float aq[4], ak[4];
    int warp = t >> 5, lane = t & 31;
    if (lane == 0) { aq[warp] = sq; ak[warp] = sk; }
    __syncthreads();
    float tq = aq[0] + aq[1] + aq[2] + aq[3];
    float tk = ak[0] + ak[1] + ak[2] + ak[3];
    float rq = rsqrtf(tq * (1.f / HD) + EPS);
    float rk = rsqrtf(tk * (1.f / HD) + EPS);

    bool is_img = (s < S_IMG);
    float qn = qv * rq * (is_img ? qw_img[t] : qw_txt[t]);
    float kn = kv * rk * (is_img ? kw_img[t] : kw_txt[t]);

    __shared__ float qs[HD], ks[HD];
    qs[t] = qn; ks[t] = kn;
    __syncthreads();

    if (is_img) {
        int p = t >> 1;
        float c  = cosp[(size_t)s * (HD / 2) + p];
        float sn = sinp[(size_t)s * (HD / 2) + p];
        float x1q = qs[p * 2], x2q = qs[p * 2 + 1];
        float x1k = ks[p * 2], x2k = ks[p * 2 + 1];
        if (t & 1) { qn = x2q * c + x1q * sn; kn = x2k * c + x1k * sn; }
        else       { qn = x1q * c - x2q * sn; kn = x1k * c - x2k * sn; }
    }

    size_t o = ((size_t)h * S_ALL + s) * HD + t;
    __nv_bfloat16 qh = __float2bfloat16_rn(qn);
    __nv_bfloat16 kh = __float2bfloat16_rn(kn);
    __nv_bfloat16 vh = __float2bfloat16_rn(vv);
    g_qh[o] = qh; g_ql[o] = __float2bfloat16_rn(qn - __bfloat162float(qh));
    g_kh[o] = kh; g_kl[o] = __float2bfloat16_rn(kn - __bfloat162float(kh));
    g_vh[o] = vh; g_vl[o] = __float2bfloat16_rn(vv - __bfloat162float(vh));
}

// ---------------------------------------------------------------------------
// HMMA flash attention (unchanged from R8/R12/R14 passing version)
// ---------------------------------------------------------------------------
#define LDQ 136
#define Q_BYTES2 (128 * LDQ * 2)
#define KV_ARR  (64 * LDQ * 2)
#define KV_BUF  (4 * KV_ARR)
#define ATTN_SMEM2 (2 * Q_BYTES2 + 2 * KV_BUF)

__global__ void __launch_bounds__(256, 1)
k_attn_mma(__nv_bfloat16* __restrict__ ohi, __nv_bfloat16* __restrict__ olo)
{
    extern __shared__ char smc[];
    const uint32_t sb = smem_u32(smc);
    const int tid = threadIdx.x, warp = tid >> 5, lane = tid & 31;
    const int h = blockIdx.y;
    const int q0 = blockIdx.x * 128;

    const uint32_t sQh = sb, sQl = sb + Q_BYTES2;

    {
        const __nv_bfloat16* gq = g_qh + ((size_t)h * S_ALL + q0) * HD;
        const __nv_bfloat16* gl = g_ql + ((size_t)h * S_ALL + q0) * HD;
        #pragma unroll
        for (int it = 0; it < 8; it++) {
            int idx = tid + it * 256;
            int row = idx >> 4, c = idx & 15;
            uint32_t dst = (uint32_t)(row * LDQ + c * 8) * 2;
            CP16(sQh + dst, gq + (size_t)row * HD + c * 8);
            CP16(sQl + dst, gl + (size_t)row * HD + c * 8);
        }
        CP_COMMIT();
    }

    auto issue_kv = [&](int t) {
        const uint32_t kb = sb + 2 * Q_BYTES2 + (t & 1) * KV_BUF;
        const size_t src0 = ((size_t)h * S_ALL + t * 64) * HD;
        #pragma unroll
        for (int it = 0; it < 4; it++) {
            int idx = tid + it * 256;
            int row = idx >> 4, c = idx & 15;
            size_t so = src0 + (size_t)row * HD + c * 8;
            uint32_t dst = kb + (uint32_t)(row * LDQ + c * 8) * 2;
            CP16(dst,              g_kh + so);
            CP16(dst + KV_ARR,     g_kl + so);
            CP16(dst + 2 * KV_ARR, g_vh + so);
            CP16(dst + 3 * KV_ARR, g_vl + so);
        }
        CP_COMMIT();
    };

    issue_kv(0);
    CP_WAIT0();
    __syncthreads();

    float oacc[16][4];
    #pragma unroll
    for (int j = 0; j < 16; j++)
        #pragma unroll
        for (int r = 0; r < 4; r++) oacc[j][r] = 0.f;
    float m0 = -1e30f, m1 = -1e30f, l0 = 0.f, l1 = 0.f;
    const float scale = 0.08838834764831845f;

    const int lrow = lane & 15;
    const int lkh  = lane >> 4;
    const int btn  = lane & 7;
    const int btk  = (lane >> 3) & 1;

    for (int t = 0; t < 36; t++) {
        if (t + 1 < 36) issue_kv(t + 1);

        const uint32_t kb  = sb + 2 * Q_BYTES2 + (t & 1) * KV_BUF;
        const uint32_t sKh = kb, sKl = kb + KV_ARR;
        const uint32_t sVh = kb + 2 * KV_ARR, sVl = kb + 3 * KV_ARR;

        float sacc[8][4];
        #pragma unroll
        for (int j = 0; j < 8; j++)
            #pragma unroll
            for (int r = 0; r < 4; r++) sacc[j][r] = 0.f;

        #pragma unroll
        for (int ks = 0; ks < 8; ks++) {
            const int kbft = ks * 16;
            uint32_t qh4[4], ql4[4];
            uint32_t aoff = (uint32_t)((warp * 16 + lrow) * LDQ + kbft + lkh * 8) * 2;
            ldsm_x4(qh4, sQh + aoff);
            ldsm_x4(ql4, sQl + aoff);
            #pragma unroll
            for (int j = 0; j < 8; j++) {
                uint32_t kh2[2], kl2[2];
                uint32_t boff = (uint32_t)((j * 8 + btn) * LDQ + kbft + btk * 8) * 2;
                ldsm_x2(kh2, sKh + boff);
                ldsm_x2(kl2, sKl + boff);
                mma_bf16(sacc[j], qh4, kh2);
                mma_bf16(sacc[j], qh4, kl2);
                mma_bf16(sacc[j], ql4, kh2);
            }
        }

        float mr0 = -1e30f, mr1 = -1e30f;
        #pragma unroll
        for (int j = 0; j < 8; j++) {
            sacc[j][0] *= scale; sacc[j][1] *= scale;
            sacc[j][2] *= scale; sacc[j][3] *= scale;
            mr0 = fmaxf(mr0, fmaxf(sacc[j][0], sacc[j][1]));
            mr1 = fmaxf(mr1, fmaxf(sacc[j][2], sacc[j][3]));
        }
        mr0 = fmaxf(mr0, __shfl_xor_sync(0xffffffffu, mr0, 1));
        mr0 = fmaxf(mr0, __shfl_xor_sync(0xffffffffu, mr0, 2));
        mr1 = fmaxf(mr1, __shfl_xor_sync(0xffffffffu, mr1, 1));
        mr1 = fmaxf(mr1, __shfl_xor_sync(0xffffffffu, mr1, 2));
        float mn0 = fmaxf(m0, mr0), mn1 = fmaxf(m1, mr1);
        float a0 = __expf(m0 - mn0), a1 = __expf(m1 - mn1);
        m0 = mn0; m1 = mn1;

        float rs0 = 0.f, rs1 = 0.f;
        #pragma unroll
        for (int j = 0; j < 8; j++) {
            sacc[j][0] = __expf(sacc[j][0] - mn0);
            sacc[j][1] = __expf(sacc[j][1] - mn0);
            sacc[j][2] = __expf(sacc[j][2] - mn1);
            sacc[j][3] = __expf(sacc[j][3] - mn1);
            rs0 += sacc[j][0] + sacc[j][1];
            rs1 += sacc[j][2] + sacc[j][3];
        }
        rs0 += __shfl_xor_sync(0xffffffffu, rs0, 1);
        rs0 += __shfl_xor_sync(0xffffffffu, rs0, 2);
        rs1 += __shfl_xor_sync(0xffffffffu, rs1, 1);
        rs1 += __shfl_xor_sync(0xffffffffu, rs1, 2);
        l0 = l0 * a0 + rs0;
        l1 = l1 * a1 + rs1;

        uint32_t phi[4][4], plo[4][4];
        #pragma unroll
        for (int tt = 0; tt < 4; tt++) {
            __nv_bfloat162 lo2;
            __nv_bfloat162 hi2;
            hi2 = bf2hi(sacc[2*tt][0],   sacc[2*tt][1],   lo2);
            phi[tt][0] = *(uint32_t*)&hi2; plo[tt][0] = *(uint32_t*)&lo2;
            hi2 = bf2hi(sacc[2*tt][2],   sacc[2*tt][3],   lo2);
            phi[tt][1] = *(uint32_t*)&hi2; plo[tt][1] = *(uint32_t*)&lo2;
            hi2 = bf2hi(sacc[2*tt+1][0], sacc[2*tt+1][1], lo2);
            phi[tt][2] = *(uint32_t*)&hi2; plo[tt][2] = *(uint32_t*)&lo2;
            hi2 = bf2hi(sacc[2*tt+1][2], sacc[2*tt+1][3], lo2);
            phi[tt][3] = *(uint32_t*)&hi2; plo[tt][3] = *(uint32_t*)&lo2;
        }

        #pragma unroll
        for (int j = 0; j < 16; j++) {
            oacc[j][0] *= a0; oacc[j][1] *= a0;
            oacc[j][2] *= a1; oacc[j][3] *= a1;
        }

        #pragma unroll
        for (int tt = 0; tt < 4; tt++) {
            #pragma unroll
            for (int j = 0; j < 16; j++) {
                uint32_t vh2[2], vl2[2];
                uint32_t boff = (uint32_t)((tt * 16 + lrow) * LDQ + j * 8) * 2;
                ldsm_x2_t(vh2, sVh + boff);
                ldsm_x2_t(vl2, sVl + boff);
                mma_bf16(oacc[j], phi[tt], vh2);
                mma_bf16(oacc[j], plo[tt], vh2);
                mma_bf16(oacc[j], phi[tt], vl2);
            }
        }

        if (t + 1 < 36) CP_WAIT0();
        __syncthreads();
    }

    float inv0 = 1.f / l0, inv1 = 1.f / l1;
    int r0 = q0 + warp * 16 + (lane >> 2);
    int r1 = r0 + 8;
    #pragma unroll
    for (int j = 0; j < 16; j++) {
        int col = h * HD + j * 8 + (lane & 3) * 2;
        __nv_bfloat162 lo2;
        __nv_bfloat162 hi2 = bf2hi(oacc[j][0] * inv0, oacc[j][1] * inv0, lo2);
        size_t o0 = (size_t)r0 * HID + col;
        *(__nv_bfloat162*)(ohi + o0) = hi2;
        *(__nv_bfloat162*)(olo + o0) = lo2;
        hi2 = bf2hi(oacc[j][2] * inv1, oacc[j][3] * inv1, lo2);
        size_t o1 = (size_t)r1 * HID + col;
        *(__nv_bfloat162*)(ohi + o1) = hi2;
        *(__nv_bfloat162*)(olo + o1) = lo2;
    }
}

// ---------------------------------------------------------------------------
// launch
// ---------------------------------------------------------------------------
extern "C" void kernel_launch(void* const* d_in, const int* in_sizes, int n_in,
                              void* d_out, int out_size)
{
    const float* img        = (const float*)d_in[0];
    const float* txt        = (const float*)d_in[1];
    const float* vec        = (const float*)d_in[2];
    const float* cosp       = (const float*)d_in[3];
    const float* sinp       = (const float*)d_in[4];
    const float* img_mod_w  = (const float*)d_in[5];
    const float* img_mod_b  = (const float*)d_in[6];
    const float* img_qkv_w  = (const float*)d_in[7];
    const float* img_qkv_b  = (const float*)d_in[8];
    const float* img_qn_w   = (const float*)d_in[9];
    const float* img_kn_w   = (const float*)d_in[10];
    const float* img_proj_w = (const float*)d_in[11];
    const float* img_proj_b = (const float*)d_in[12];
    const float* img_mlp_w1 = (const float*)d_in[13];
    const float* img_mlp_b1 = (const float*)d_in[14];
    const float* img_mlp_w2 = (const float*)d_in[15];
    const float* img_mlp_b2 = (const float*)d_in[16];
    const float* txt_mod_w  = (const float*)d_in[17];
    const float* txt_mod_b  = (const float*)d_in[18];
    const float* txt_qkv_w  = (const float*)d_in[19];
    const float* txt_qkv_b  = (const float*)d_in[20];
    const float* txt_qn_w   = (const float*)d_in[21];
    const float* txt_kn_w   = (const float*)d_in[22];
    const float* txt_proj_w = (const float*)d_in[23];
    const float* txt_proj_b = (const float*)d_in[24];
    const float* txt_mlp_w1 = (const float*)d_in[25];
    const float* txt_mlp_b1 = (const float*)d_in[26];
    const float* txt_mlp_w2 = (const float*)d_in[27];
    const float* txt_mlp_b2 = (const float*)d_in[28];
    float* out = (float*)d_out;

    float *mod_i, *mod_t, *qkv, *res;
    __nv_bfloat16 *xh, *xl, *x2h, *x2l, *ath, *atl, *hh, *hl;
    __nv_bfloat16 *wiq_h, *wiq_l, *wip_h, *wip_l, *wi1_h, *wi1_l, *wi2_h, *wi2_l;
    __nv_bfloat16 *wtq_h, *wtq_l, *wtp_h, *wtp_l, *wt1_h, *wt1_l, *wt2_h, *wt2_l;

    cudaGetSymbolAddress((void**)&mod_i, g_mod_i);
    cudaGetSymbolAddress((void**)&mod_t, g_mod_t);
    cudaGetSymbolAddress((void**)&qkv,   g_qkv);
    cudaGetSymbolAddress((void**)&res,   g_res);
    cudaGetSymbolAddress((void**)&xh,  g_xln_h);  cudaGetSymbolAddress((void**)&xl,  g_xln_l);
    cudaGetSymbolAddress((void**)&x2h, g_x2_h);   cudaGetSymbolAddress((void**)&x2l, g_x2_l);
    cudaGetSymbolAddress((void**)&ath, g_at_h);   cudaGetSymbolAddress((void**)&atl, g_at_l);
    cudaGetSymbolAddress((void**)&hh,  g_hh);     cudaGetSymbolAddress((void**)&hl,  g_hl);
    cudaGetSymbolAddress((void**)&wiq_h, g_wiqkv_h); cudaGetSymbolAddress((void**)&wiq_l, g_wiqkv_l);
    cudaGetSymbolAddress((void**)&wip_h, g_wipro_h); cudaGetSymbolAddress((void**)&wip_l, g_wipro_l);
    cudaGetSymbolAddress((void**)&wi1_h, g_wiw1_h);  cudaGetSymbolAddress((void**)&wi1_l, g_wiw1_l);
    cudaGetSymbolAddress((void**)&wi2_h, g_wiw2_h);  cudaGetSymbolAddress((void**)&wi2_l, g_wiw2_l);
    cudaGetSymbolAddress((void**)&wtq_h, g_wtqkv_h); cudaGetSymbolAddress((void**)&wtq_l, g_wtqkv_l);
    cudaGetSymbolAddress((void**)&wtp_h, g_wtpro_h); cudaGetSymbolAddress((void**)&wtp_l, g_wtpro_l);
    cudaGetSymbolAddress((void**)&wt1_h, g_wtw1_h);  cudaGetSymbolAddress((void**)&wt1_l, g_wtw1_l);
    cudaGetSymbolAddress((void**)&wt2_h, g_wtw2_h);  cudaGetSymbolAddress((void**)&wt2_l, g_wtw2_l);

    cudaFuncSetAttribute(k_attn_mma, cudaFuncAttributeMaxDynamicSharedMemorySize,
                         (int)ATTN_SMEM2);
    cudaFuncSetAttribute(k_gemm2<0>, cudaFuncAttributeMaxDynamicSharedMemorySize, GEMM_SMEM);
    cudaFuncSetAttribute(k_gemm2<1>, cudaFuncAttributeMaxDynamicSharedMemorySize, GEMM_SMEM);
    cudaFuncSetAttribute(k_gemm2<2>, cudaFuncAttributeMaxDynamicSharedMemorySize, GEMM_SMEM);

    // prologue: weight splits + modulation + LN
    k_split4b<<<dim3((HID * QKV3) / 2048, 2), 256>>>(
        (const float4*)img_qkv_w, (uint4*)wiq_h, (uint4*)wiq_l,
        (const float4*)txt_qkv_w, (uint4*)wtq_h, (uint4*)wtq_l);
    k_mod2<<<dim3(MOD6 / 256, 2), 256>>>(vec, img_mod_w, img_mod_b,
                                         txt_mod_w, txt_mod_b, mod_i, mod_t);
    k_ln_mod2<<<S_ALL, 256>>>(img, txt, mod_i, mod_i + HID,
                              mod_t, mod_t + HID, xh, xl);
    k_split4b<<<dim3((HID * HID) / 2048, 2), 256>>>(
        (const float4*)img_proj_w, (uint4*)wip_h, (uint4*)wip_l,
        (const float4*)txt_proj_w, (uint4*)wtp_h, (uint4*)wtp_l);
    k_split4b<<<dim3((HID * MLPD) / 2048, 2), 256>>>(
        (const float4*)img_mlp_w1, (uint4*)wi1_h, (uint4*)wi1_l,
        (const float4*)txt_mlp_w1, (uint4*)wt1_h, (uint4*)wt1_l);

    // merged QKV GEMM (grid: x = N-strips, y = M-blocks — R14 baseline)
    k_gemm2<0><<<dim3(QKV3 / 128, MBALL), 256, GEMM_SMEM>>>(
        xh, xl, wiq_h, wiq_l, wtq_h, wtq_l, img_qkv_b, txt_qkv_b,
        nullptr, nullptr, nullptr, nullptr, qkv, nullptr, nullptr,
        QKV3, HID);

    k_split4b<<<dim3((HID * MLPD) / 2048, 2), 256>>>(
        (const float4*)img_mlp_w2, (uint4*)wi2_h, (uint4*)wi2_l,
        (const float4*)txt_mlp_w2, (uint4*)wt2_h, (uint4*)wt2_l);

    // rms-norm + rope + scatter
    k_qkv_post<<<dim3(S_ALL, NH), HD>>>(qkv, img_qn_w, img_kn_w,
                                        txt_qn_w, txt_kn_w, cosp, sinp);

    // attention
    k_attn_mma<<<dim3(S_ALL / 128, NH), 256, ATTN_SMEM2>>>(ath, atl);

    // output projection + gated residual
    k_gemm2<2><<<dim3(HID / 128, MBALL), 256, GEMM_SMEM>>>(
        ath, atl, wip_h, wip_l, wtp_h, wtp_l, img_proj_b, txt_proj_b,
        img, txt, mod_i + 2 * HID, mod_t + 2 * HID, res, nullptr, nullptr,
        HID, HID);

    // LN + mlp modulation
    k_ln_mod2<<<S_ALL, 256>>>(res, res + IMGOFF, mod_i + 3 * HID,
                              mod_i + 4 * HID, mod_t + 3 * HID,
                              mod_t + 4 * HID, x2h, x2l);

    // MLP up + gelu
    k_gemm2<1><<<dim3(MLPD / 128, MBALL), 256, GEMM_SMEM>>>(
        x2h, x2l, wi1_h, wi1_l, wt1_h, wt1_l, img_mlp_b1, txt_mlp_b1,
        nullptr, nullptr, nullptr, nullptr, nullptr, hh, hl,
        MLPD, HID);

    // MLP down + gated residual -> final output
    k_gemm2<2><<<dim3(HID / 128, MBALL), 256, GEMM_SMEM>>>(
        hh, hl, wi2_h, wi2_l, wt2_h, wt2_l, img_mlp_b2, txt_mlp_b2,
        res, res + IMGOFF, mod_i + 5 * HID, mod_t + 5 * HID, out,
        nullptr, nullptr, HID, MLPD);
}